// round 5
// baseline (speedup 1.0000x reference)
#include <cuda_runtime.h>
#include <cuda_fp16.h>
#include <math.h>
#include <stdint.h>

#define NTOK 4096
#define HD   1024
#define FF   4096
#define NE   8
#define PADM 128
#define MAXR 9216
#define MTILES (MAXR / PADM)      // 72
#define BN   256
#define BK   32
#define SAROW 40                         // smem row stride in halves (80B)
#define STAGE_B ((128 + BN) * SAROW * 2) // A + B per stage = 30720
#define NSTAGES 4
#define SM_TOT (NSTAGES * STAGE_B)       // 122880

// ---------------- scratch ----------------
__device__ __half g_xh[(size_t)MAXR * HD];
__device__ __half g_w1t[(size_t)NE * FF * HD];   // [e][n(FF)][k(HD)]
__device__ __half g_w2t[(size_t)NE * HD * FF];   // [e][n(HD)][k(FF)]
__device__ __half g_h1[(size_t)MAXR * FF];
__device__ float  g_o[(size_t)MAXR * HD];
__device__ int    g_tope[NTOK * 2];
__device__ float  g_topw[NTOK * 2];
__device__ int    g_rows[MAXR];
__device__ int    g_t2r [NTOK * 2];
__device__ int    g_counts[NE];
__device__ int    g_cursor[NE];
__device__ int    g_poff[NE + 1];

// ---------------- PTX helpers ----------------
__device__ __forceinline__ uint32_t smem_u32(const void* p) {
    uint32_t a;
    asm("{ .reg .u64 t; cvta.to.shared.u64 t, %1; cvt.u32.u64 %0, t; }" : "=r"(a) : "l"(p));
    return a;
}
#define CPA16(dst, src) asm volatile("cp.async.cg.shared.global [%0], [%1], 16;" :: "r"(dst), "l"(src))
#define CPA_COMMIT()    asm volatile("cp.async.commit_group;" ::: "memory")
#define CPA_WAIT2()     asm volatile("cp.async.wait_group 2;" ::: "memory")
#define LDSM4(r0, r1, r2, r3, a) \
    asm volatile("ldmatrix.sync.aligned.m8n8.x4.shared.b16 {%0,%1,%2,%3}, [%4];" \
                 : "=r"(r0), "=r"(r1), "=r"(r2), "=r"(r3) : "r"(a))
#define MMA16816(d, a, b) \
    asm volatile("mma.sync.aligned.m16n8k16.row.col.f32.f16.f16.f32 " \
                 "{%0,%1,%2,%3}, {%4,%5,%6,%7}, {%8,%9}, {%0,%1,%2,%3};" \
                 : "+f"((d)[0]), "+f"((d)[1]), "+f"((d)[2]), "+f"((d)[3]) \
                 : "r"((a)[0]), "r"((a)[1]), "r"((a)[2]), "r"((a)[3]), "r"((b)[0]), "r"((b)[1]))

__device__ __forceinline__ float gelu_f(float v) {
    const float c = 0.7978845608028654f;
    float u = c * (v + 0.044715f * v * v * v);
    return 0.5f * v * (1.f + tanhf(u));
}

// ---------------- 1. init ----------------
__global__ void init_kernel() {
    int i = blockIdx.x * blockDim.x + threadIdx.x;
    if (i < MAXR) g_rows[i] = -1;
    if (i < NE) { g_counts[i] = 0; g_cursor[i] = 0; }
}

// ---------------- 2. router ----------------
__global__ __launch_bounds__(128) void router_kernel(const float* __restrict__ x,
                                                     const float* __restrict__ Wg,
                                                     float* __restrict__ logits) {
    int t = blockIdx.x;
    const float* xr = x + (size_t)t * HD;
    float acc[NE];
#pragma unroll
    for (int e = 0; e < NE; e++) acc[e] = 0.f;
    for (int j = threadIdx.x; j < HD; j += 128) {
        float xv = xr[j];
        const float4* w4 = reinterpret_cast<const float4*>(Wg + (size_t)j * NE);
        float4 wa = w4[0], wb = w4[1];
        acc[0] += xv * wa.x; acc[1] += xv * wa.y; acc[2] += xv * wa.z; acc[3] += xv * wa.w;
        acc[4] += xv * wb.x; acc[5] += xv * wb.y; acc[6] += xv * wb.z; acc[7] += xv * wb.w;
    }
    __shared__ float s[4][NE];
    int lane = threadIdx.x & 31, warp = threadIdx.x >> 5;
#pragma unroll
    for (int e = 0; e < NE; e++) {
        float v = acc[e];
#pragma unroll
        for (int o = 16; o; o >>= 1) v += __shfl_down_sync(0xffffffffu, v, o);
        if (lane == 0) s[warp][e] = v;
    }
    __syncthreads();
    if (threadIdx.x == 0) {
        float l[NE];
#pragma unroll
        for (int e = 0; e < NE; e++) {
            l[e] = s[0][e] + s[1][e] + s[2][e] + s[3][e];
            logits[(size_t)t * NE + e] = l[e];
        }
        int e0 = 0;
#pragma unroll
        for (int e = 1; e < NE; e++) if (l[e] > l[e0]) e0 = e;
        int e1 = (e0 == 0) ? 1 : 0;
#pragma unroll
        for (int e = 0; e < NE; e++) if (e != e0 && l[e] > l[e1]) e1 = e;
        float w0 = 1.f / (1.f + expf(l[e1] - l[e0]));
        float w1 = 1.f - w0;
        g_tope[t * 2] = e0; g_tope[t * 2 + 1] = e1;
        g_topw[t * 2] = w0; g_topw[t * 2 + 1] = w1;
        atomicAdd(&g_counts[e0], 1);
        atomicAdd(&g_counts[e1], 1);
    }
}

// ---------------- 3. offsets ----------------
__global__ void offsets_kernel() {
    int off = 0;
#pragma unroll
    for (int e = 0; e < NE; e++) {
        g_poff[e] = off;
        off += (g_counts[e] + PADM - 1) / PADM * PADM;
    }
    g_poff[NE] = off;
}

// ---------------- 4. scatter ----------------
__global__ void scatter_kernel() {
    int t = blockIdx.x * blockDim.x + threadIdx.x;
    if (t >= NTOK) return;
#pragma unroll
    for (int k = 0; k < 2; k++) {
        int e = g_tope[t * 2 + k];
        int slot = atomicAdd(&g_cursor[e], 1);
        int r = g_poff[e] + slot;
        g_rows[r] = t;
        g_t2r[t * 2 + k] = r;
    }
}

// ---------------- 5a. gather X -> fp16 ----------------
__global__ __launch_bounds__(256) void xsplit_kernel(const float* __restrict__ x) {
    int r = blockIdx.x;
    int tok = g_rows[r];
    int c = threadIdx.x * 4;
    float4 v = make_float4(0.f, 0.f, 0.f, 0.f);
    if (tok >= 0) v = *reinterpret_cast<const float4*>(x + (size_t)tok * HD + c);
    __half h[4];
    h[0] = __float2half_rn(v.x); h[1] = __float2half_rn(v.y);
    h[2] = __float2half_rn(v.z); h[3] = __float2half_rn(v.w);
    *reinterpret_cast<uint2*>(&g_xh[(size_t)r * HD + c]) = *reinterpret_cast<uint2*>(h);
}

// ---------------- 5b. transpose weights to [e][n][k] fp16 ----------------
__global__ __launch_bounds__(256) void wsplit_kernel(const float* __restrict__ W,
                                                     __half* __restrict__ Wt,
                                                     int K, int N) {
    __shared__ float t[32][33];
    int e = blockIdx.z;
    int k0 = blockIdx.y * 32, n0 = blockIdx.x * 32;
    const float* src = W + (size_t)e * K * N;
    int tx = threadIdx.x, ty = threadIdx.y;
#pragma unroll
    for (int i = 0; i < 4; i++) {
        int k = ty + i * 8;
        t[k][tx] = src[(size_t)(k0 + k) * N + n0 + tx];
    }
    __syncthreads();
#pragma unroll
    for (int i = 0; i < 4; i++) {
        int n = ty + i * 8;
        Wt[((size_t)e * N + n0 + n) * K + k0 + tx] = __float2half_rn(t[tx][n]);
    }
}

// ---------------- 6. HMMA grouped GEMM (128x256x32, 64x64 warp tile) ----------------
template <int KTOT, bool GELU>
__global__ __launch_bounds__(256, 1) void mma_gemm_kernel(
    const __half* __restrict__ Amat, const __half* __restrict__ Bmat, int Ndim,
    __half* __restrict__ OutH, float* __restrict__ OutF)
{
    extern __shared__ char smem[];
    uint32_t sb = smem_u32(smem);
    int tid = threadIdx.x;
    int wid = tid >> 5, lane = tid & 31;

    int r0 = blockIdx.x * PADM;
    if (r0 >= g_poff[NE]) return;
    int e = 0;
#pragma unroll
    for (int i = 1; i < NE; i++) if (r0 >= g_poff[i]) e = i;
    int n0 = blockIdx.y * BN;
    const __half* Bp = Bmat + ((size_t)e * Ndim + n0) * KTOT;
    const __half* Ap = Amat + (size_t)r0 * KTOT;

    const int NS = KTOT / BK;
    int wm = wid >> 2, wn = wid & 3;   // 2 x 4 warps, 64x64 warp tile

    float acc[4][8][4];
#pragma unroll
    for (int mi = 0; mi < 4; mi++)
#pragma unroll
        for (int ni = 0; ni < 8; ni++)
#pragma unroll
            for (int q = 0; q < 4; q++) acc[mi][ni][q] = 0.f;

    // per stage: A 128 rows (512 x 16B), B 256 rows (1024 x 16B) => 6 iters x 256 thr
    auto load_stage = [&](int s, int bs) {
        uint32_t base = sb + bs * STAGE_B;
#pragma unroll
        for (int it = 0; it < 6; it++) {
            int idx = tid + it * 256;
            if (it < 2) {                      // A: idx 0..511
                int row = idx >> 2, seg = idx & 3;
                CPA16(base + row * (SAROW * 2) + seg * 16,
                      Ap + (size_t)row * KTOT + s * BK + seg * 8);
            } else {                           // B: idx 512..1535
                int j = idx - 512;
                int row = j >> 2, seg = j & 3;
                CPA16(base + 128 * (SAROW * 2) + row * (SAROW * 2) + seg * 16,
                      Bp + (size_t)row * KTOT + s * BK + seg * 8);
            }
        }
    };

    load_stage(0, 0); CPA_COMMIT();
    load_stage(1, 1); CPA_COMMIT();
    load_stage(2, 2); CPA_COMMIT();

    int lr = lane & 15, lc = lane >> 4;
    for (int s = 0; s < NS; s++) {
        CPA_WAIT2();
        __syncthreads();
        if (s + 3 < NS) load_stage(s + 3, (s + 3) % NSTAGES);
        CPA_COMMIT();

        uint32_t aB = sb + (s % NSTAGES) * STAGE_B;
        uint32_t bB = aB + 128 * (SAROW * 2);
#pragma unroll
        for (int ks = 0; ks < 2; ks++) {
            uint32_t ah[4][4], bf[8][2];
#pragma unroll
            for (int bi = 0; bi < 4; bi++) {
                uint32_t t0, t1, t2, t3;
                uint32_t addr = bB + (wn * 64 + bi * 16 + lr) * (SAROW * 2) + ks * 32 + lc * 16;
                LDSM4(t0, t1, t2, t3, addr);
                bf[bi * 2 + 0][0] = t0; bf[bi * 2 + 0][1] = t2;
                bf[bi * 2 + 1][0] = t1; bf[bi * 2 + 1][1] = t3;
            }
#pragma unroll
            for (int mi = 0; mi < 4; mi++) {
                uint32_t addr = aB + (wm * 64 + mi * 16 + lr) * (SAROW * 2) + ks * 32 + lc * 16;
                LDSM4(ah[mi][0], ah[mi][1], ah[mi][2], ah[mi][3], addr);
            }
#pragma unroll
            for (int mi = 0; mi < 4; mi++)
#pragma unroll
                for (int ni = 0; ni < 8; ni++)
                    MMA16816(acc[mi][ni], ah[mi], bf[ni]);
        }
        __syncthreads();
    }

    int rbase = r0 + wm * 64 + (lane >> 2);
    int cbase = n0 + wn * 64 + (lane & 3) * 2;
#pragma unroll
    for (int mi = 0; mi < 4; mi++) {
#pragma unroll
        for (int ni = 0; ni < 8; ni++) {
#pragma unroll
            for (int half = 0; half < 2; half++) {
                int r = rbase + mi * 16 + half * 8;
                int c = cbase + ni * 8;
                float v0 = acc[mi][ni][half * 2 + 0];
                float v1 = acc[mi][ni][half * 2 + 1];
                if (GELU) {
                    __half2 hh = __halves2half2(__float2half_rn(gelu_f(v0)),
                                                __float2half_rn(gelu_f(v1)));
                    *reinterpret_cast<__half2*>(&OutH[(size_t)r * FF + c]) = hh;
                } else {
                    float2 o; o.x = v0; o.y = v1;
                    *reinterpret_cast<float2*>(&OutF[(size_t)r * HD + c]) = o;
                }
            }
        }
    }
}

// ---------------- 7. combine ----------------
__global__ __launch_bounds__(256) void combine_kernel(float* __restrict__ out) {
    int t = blockIdx.x;
    int r0 = g_t2r[t * 2], r1 = g_t2r[t * 2 + 1];
    float w0 = g_topw[t * 2], w1 = g_topw[t * 2 + 1];
    int c = threadIdx.x * 4;
    float4 a = *reinterpret_cast<const float4*>(g_o + (size_t)r0 * HD + c);
    float4 b = *reinterpret_cast<const float4*>(g_o + (size_t)r1 * HD + c);
    float4 o;
    o.x = w0 * a.x + w1 * b.x;
    o.y = w0 * a.y + w1 * b.y;
    o.z = w0 * a.z + w1 * b.z;
    o.w = w0 * a.w + w1 * b.w;
    *reinterpret_cast<float4*>(out + (size_t)t * HD + c) = o;
}

// ---------------- 8. aux loss ----------------
__global__ __launch_bounds__(256) void aux_kernel(const float* __restrict__ logits,
                                                  float* __restrict__ aux_out) {
    __shared__ float red[256][17];
    float acc[NE], freq[NE];
#pragma unroll
    for (int e = 0; e < NE; e++) { acc[e] = 0.f; freq[e] = 0.f; }
    float z = 0.f;
    for (int t = threadIdx.x; t < NTOK; t += 256) {
        float l[NE];
#pragma unroll
        for (int e = 0; e < NE; e++) l[e] = logits[(size_t)t * NE + e];
        float m = l[0];
#pragma unroll
        for (int e = 1; e < NE; e++) m = fmaxf(m, l[e]);
        float p[NE], s = 0.f;
#pragma unroll
        for (int e = 0; e < NE; e++) { p[e] = expf(l[e] - m); s += p[e]; }
        float inv = 1.f / s;
#pragma unroll
        for (int e = 0; e < NE; e++) acc[e] += p[e] * inv;
        float lse = m + logf(s);
        z += lse * lse;
        int e0 = 0;
#pragma unroll
        for (int e = 1; e < NE; e++) if (l[e] > l[e0]) e0 = e;
        int e1 = (e0 == 0) ? 1 : 0;
#pragma unroll
        for (int e = 0; e < NE; e++) if (e != e0 && l[e] > l[e1]) e1 = e;
        freq[e0] += 1.f; freq[e1] += 1.f;
    }
    int tid = threadIdx.x;
#pragma unroll
    for (int e = 0; e < NE; e++) { red[tid][e] = acc[e]; red[tid][8 + e] = freq[e]; }
    red[tid][16] = z;
    __syncthreads();
    for (int s2 = 128; s2; s2 >>= 1) {
        if (tid < s2)
#pragma unroll
            for (int c = 0; c < 17; c++) red[tid][c] += red[tid + s2][c];
        __syncthreads();
    }
    if (tid == 0) {
        float sp = 0.f, sf = 0.f;
#pragma unroll
        for (int e = 0; e < NE; e++) { sp += red[0][e]; sf += red[0][8 + e]; }
        float sw = 0.f;
#pragma unroll
        for (int e = 0; e < NE; e++) sw += (red[0][e] / sp) * (red[0][8 + e] / sf);
        sw *= (float)NE;
        float zl = red[0][16] / (float)NTOK;
        aux_out[0] = sw + 0.1f * zl;
    }
}

// ---------------- entry ----------------
extern "C" void kernel_launch(void* const* d_in, const int* in_sizes, int n_in,
                              void* d_out, int out_size) {
    const float* x  = (const float*)d_in[0];
    const float* Wg = (const float*)d_in[1];
    const float* W1 = (const float*)d_in[2];
    const float* W2 = (const float*)d_in[3];
    float* out    = (float*)d_out;
    float* logits = out + (size_t)NTOK * HD;
    float* aux    = logits + (size_t)NTOK * NE;

    cudaFuncSetAttribute(mma_gemm_kernel<HD, true>,
                         cudaFuncAttributeMaxDynamicSharedMemorySize, SM_TOT);
    cudaFuncSetAttribute(mma_gemm_kernel<FF, false>,
                         cudaFuncAttributeMaxDynamicSharedMemorySize, SM_TOT);

    __half *xh, *w1t, *w2t, *h1;
    float* o_ptr;
    cudaGetSymbolAddress((void**)&xh,  g_xh);
    cudaGetSymbolAddress((void**)&w1t, g_w1t);
    cudaGetSymbolAddress((void**)&w2t, g_w2t);
    cudaGetSymbolAddress((void**)&h1,  g_h1);
    cudaGetSymbolAddress((void**)&o_ptr, g_o);

    init_kernel<<<(MAXR + 255) / 256, 256>>>();
    router_kernel<<<NTOK, 128>>>(x, Wg, logits);
    offsets_kernel<<<1, 1>>>();
    scatter_kernel<<<(NTOK + 255) / 256, 256>>>();
    xsplit_kernel<<<MAXR, 256>>>(x);
    wsplit_kernel<<<dim3(FF / 32, HD / 32, NE), dim3(32, 8)>>>(W1, w1t, HD, FF);
    wsplit_kernel<<<dim3(HD / 32, FF / 32, NE), dim3(32, 8)>>>(W2, w2t, FF, HD);
    mma_gemm_kernel<HD, true><<<dim3(MTILES, FF / BN), 256, SM_TOT>>>(xh, w1t, FF, h1, nullptr);
    mma_gemm_kernel<FF, false><<<dim3(MTILES, HD / BN), 256, SM_TOT>>>(h1, w2t, HD, nullptr, o_ptr);
    combine_kernel<<<NTOK, 256>>>(out);
    aux_kernel<<<1, 256>>>(logits, aux);
}

// round 6
// speedup vs baseline: 1.0251x; 1.0251x over previous
#include <cuda_runtime.h>
#include <cuda_fp16.h>
#include <math.h>
#include <stdint.h>

#define NTOK 4096
#define HD   1024
#define FF   4096
#define NE   8
#define PADM 128
#define MAXR 9216
#define MTILES (MAXR / PADM)      // 72
#define BN   128
#define BK   32
#define SAROW 40                        // A smem row stride in halves (80B)
#define A_BYTES (128 * SAROW * 2)       // 10240
#define B_BYTES (BK * BN * 2)           // 8192  (32 k-rows x 256B)
#define STAGE_B (A_BYTES + B_BYTES)     // 18432
#define NSTAGES 4
#define SM_TOT (NSTAGES * STAGE_B)      // 73728

// ---------------- scratch ----------------
__device__ __half g_xh[(size_t)MAXR * HD];
__device__ __half g_w1h[(size_t)NE * HD * FF];   // same layout as W1: [e][k][n]
__device__ __half g_w2h[(size_t)NE * FF * HD];   // same layout as W2: [e][k][n]
__device__ __half g_h1[(size_t)MAXR * FF];
__device__ float  g_o[(size_t)MAXR * HD];
__device__ int    g_tope[NTOK * 2];
__device__ float  g_topw[NTOK * 2];
__device__ int    g_rows[MAXR];
__device__ int    g_t2r [NTOK * 2];
__device__ int    g_counts[NE];
__device__ int    g_cursor[NE];
__device__ int    g_poff[NE + 1];

// ---------------- PTX helpers ----------------
__device__ __forceinline__ uint32_t smem_u32(const void* p) {
    uint32_t a;
    asm("{ .reg .u64 t; cvta.to.shared.u64 t, %1; cvt.u32.u64 %0, t; }" : "=r"(a) : "l"(p));
    return a;
}
#define CPA16(dst, src) asm volatile("cp.async.cg.shared.global [%0], [%1], 16;" :: "r"(dst), "l"(src))
#define CPA_COMMIT()    asm volatile("cp.async.commit_group;" ::: "memory")
#define CPA_WAIT2()     asm volatile("cp.async.wait_group 2;" ::: "memory")
#define LDSM4(r0, r1, r2, r3, a) \
    asm volatile("ldmatrix.sync.aligned.m8n8.x4.shared.b16 {%0,%1,%2,%3}, [%4];" \
                 : "=r"(r0), "=r"(r1), "=r"(r2), "=r"(r3) : "r"(a))
#define LDSM4T(r0, r1, r2, r3, a) \
    asm volatile("ldmatrix.sync.aligned.m8n8.x4.trans.shared.b16 {%0,%1,%2,%3}, [%4];" \
                 : "=r"(r0), "=r"(r1), "=r"(r2), "=r"(r3) : "r"(a))
#define MMA16816(d, a, b) \
    asm volatile("mma.sync.aligned.m16n8k16.row.col.f32.f16.f16.f32 " \
                 "{%0,%1,%2,%3}, {%4,%5,%6,%7}, {%8,%9}, {%0,%1,%2,%3};" \
                 : "+f"((d)[0]), "+f"((d)[1]), "+f"((d)[2]), "+f"((d)[3]) \
                 : "r"((a)[0]), "r"((a)[1]), "r"((a)[2]), "r"((a)[3]), "r"((b)[0]), "r"((b)[1]))

__device__ __forceinline__ float gelu_f(float v) {
    const float c = 0.7978845608028654f;
    float u = c * (v + 0.044715f * v * v * v);
    return 0.5f * v * (1.f + tanhf(u));
}
__device__ __forceinline__ void conv4(const float4 v, __half* dst) {
    __half h[4];
    h[0] = __float2half_rn(v.x); h[1] = __float2half_rn(v.y);
    h[2] = __float2half_rn(v.z); h[3] = __float2half_rn(v.w);
    *reinterpret_cast<uint2*>(dst) = *reinterpret_cast<uint2*>(h);
}

// ---------------- 1. init ----------------
__global__ void init_kernel() {
    int i = threadIdx.x;
    if (i < NE) { g_counts[i] = 0; g_cursor[i] = 0; }
}

// ---------------- 2. router ----------------
__global__ __launch_bounds__(128) void router_kernel(const float* __restrict__ x,
                                                     const float* __restrict__ Wg,
                                                     float* __restrict__ logits) {
    int t = blockIdx.x;
    const float* xr = x + (size_t)t * HD;
    float acc[NE];
#pragma unroll
    for (int e = 0; e < NE; e++) acc[e] = 0.f;
    for (int j = threadIdx.x; j < HD; j += 128) {
        float xv = xr[j];
        const float4* w4 = reinterpret_cast<const float4*>(Wg + (size_t)j * NE);
        float4 wa = w4[0], wb = w4[1];
        acc[0] += xv * wa.x; acc[1] += xv * wa.y; acc[2] += xv * wa.z; acc[3] += xv * wa.w;
        acc[4] += xv * wb.x; acc[5] += xv * wb.y; acc[6] += xv * wb.z; acc[7] += xv * wb.w;
    }
    __shared__ float s[4][NE];
    int lane = threadIdx.x & 31, warp = threadIdx.x >> 5;
#pragma unroll
    for (int e = 0; e < NE; e++) {
        float v = acc[e];
#pragma unroll
        for (int o = 16; o; o >>= 1) v += __shfl_down_sync(0xffffffffu, v, o);
        if (lane == 0) s[warp][e] = v;
    }
    __syncthreads();
    if (threadIdx.x == 0) {
        float l[NE];
#pragma unroll
        for (int e = 0; e < NE; e++) {
            l[e] = s[0][e] + s[1][e] + s[2][e] + s[3][e];
            logits[(size_t)t * NE + e] = l[e];
        }
        int e0 = 0;
#pragma unroll
        for (int e = 1; e < NE; e++) if (l[e] > l[e0]) e0 = e;
        int e1 = (e0 == 0) ? 1 : 0;
#pragma unroll
        for (int e = 0; e < NE; e++) if (e != e0 && l[e] > l[e1]) e1 = e;
        float w0 = 1.f / (1.f + expf(l[e1] - l[e0]));
        float w1 = 1.f - w0;
        g_tope[t * 2] = e0; g_tope[t * 2 + 1] = e1;
        g_topw[t * 2] = w0; g_topw[t * 2 + 1] = w1;
        atomicAdd(&g_counts[e0], 1);
        atomicAdd(&g_counts[e1], 1);
    }
}

// ---------------- 3. offsets ----------------
__global__ void offsets_kernel() {
    int off = 0;
#pragma unroll
    for (int e = 0; e < NE; e++) {
        g_poff[e] = off;
        off += (g_counts[e] + PADM - 1) / PADM * PADM;
    }
    g_poff[NE] = off;
}

// ---------------- 4. scatter + gather X -> fp16 (fused) ----------------
__global__ __launch_bounds__(128) void scatter_kernel(const float* __restrict__ x) {
    int t = blockIdx.x;
    __shared__ int sr[2];
    if (threadIdx.x == 0) {
#pragma unroll
        for (int k = 0; k < 2; k++) {
            int e = g_tope[t * 2 + k];
            int slot = atomicAdd(&g_cursor[e], 1);
            int r = g_poff[e] + slot;
            g_rows[r] = t;
            g_t2r[t * 2 + k] = r;
            sr[k] = r;
        }
    }
    __syncthreads();
    int r0 = sr[0], r1 = sr[1];
    int c = threadIdx.x * 8;
    float4 v0 = *reinterpret_cast<const float4*>(x + (size_t)t * HD + c);
    float4 v1 = *reinterpret_cast<const float4*>(x + (size_t)t * HD + c + 4);
    __half h[8];
    h[0] = __float2half_rn(v0.x); h[1] = __float2half_rn(v0.y);
    h[2] = __float2half_rn(v0.z); h[3] = __float2half_rn(v0.w);
    h[4] = __float2half_rn(v1.x); h[5] = __float2half_rn(v1.y);
    h[6] = __float2half_rn(v1.z); h[7] = __float2half_rn(v1.w);
    uint4 pk = *reinterpret_cast<uint4*>(h);
    *reinterpret_cast<uint4*>(&g_xh[(size_t)r0 * HD + c]) = pk;
    *reinterpret_cast<uint4*>(&g_xh[(size_t)r1 * HD + c]) = pk;
}

// ---------------- 5. streaming fp32 -> fp16 convert ----------------
__global__ __launch_bounds__(256) void wconv_kernel(const float* __restrict__ W,
                                                    __half* __restrict__ Wh, size_t n4) {
    size_t stride = (size_t)gridDim.x * 256;
    for (size_t i = (size_t)blockIdx.x * 256 + threadIdx.x; i < n4; i += stride) {
        float4 v = reinterpret_cast<const float4*>(W)[i];
        conv4(v, Wh + i * 4);
    }
}

// ---------------- 6. HMMA grouped GEMM (128x128x32, trans-B from [k][n]) ----------------
// B smem: 32 k-rows x 256B, chunk(16B)-XOR swizzle: chunk' = chunk ^ (k & 7)
template <int KTOT, bool GELU>
__global__ __launch_bounds__(256, 2) void mma_gemm_kernel(
    const __half* __restrict__ Amat, const __half* __restrict__ Bmat, int Ndim,
    __half* __restrict__ OutH, float* __restrict__ OutF,
    const float* __restrict__ ConvSrc, __half* __restrict__ ConvDst, size_t ConvN4)
{
    extern __shared__ char smem[];
    uint32_t sb = smem_u32(smem);
    int tid = threadIdx.x;
    int wid = tid >> 5, lane = tid & 31;

    // fused converter slice (last blockIdx.y row when enabled)
    if (ConvSrc != nullptr && blockIdx.y == gridDim.y - 1) {
        size_t stride = (size_t)gridDim.x * 256;
        for (size_t i = (size_t)blockIdx.x * 256 + tid; i < ConvN4; i += stride) {
            float4 v = reinterpret_cast<const float4*>(ConvSrc)[i];
            conv4(v, ConvDst + i * 4);
        }
        return;
    }

    int r0 = blockIdx.x * PADM;
    if (r0 >= g_poff[NE]) return;
    int e = 0;
#pragma unroll
    for (int i = 1; i < NE; i++) if (r0 >= g_poff[i]) e = i;
    int n0 = blockIdx.y * BN;
    const __half* Bp = Bmat + (size_t)e * KTOT * Ndim + n0;   // [k][n], row stride Ndim
    const __half* Ap = Amat + (size_t)r0 * KTOT;

    const int NS = KTOT / BK;
    int wm = wid >> 2, wn = wid & 3;

    float acc[4][4][4];
#pragma unroll
    for (int mi = 0; mi < 4; mi++)
#pragma unroll
        for (int ni = 0; ni < 4; ni++)
#pragma unroll
            for (int q = 0; q < 4; q++) acc[mi][ni][q] = 0.f;

    auto load_stage = [&](int s, int bs) {
        uint32_t base = sb + bs * STAGE_B;
#pragma unroll
        for (int it = 0; it < 4; it++) {
            int idx = tid + it * 256;
            if (idx < 512) {                   // A: 128 rows x 4 segs of 16B
                int row = idx >> 2, seg = idx & 3;
                CPA16(base + row * (SAROW * 2) + seg * 16,
                      Ap + (size_t)row * KTOT + s * BK + seg * 8);
            } else {                           // B: 32 k-rows x 16 chunks of 16B
                int j = idx - 512;
                int row = j >> 4, chunk = j & 15;
                CPA16(base + A_BYTES + row * 256 + ((chunk ^ (row & 7)) << 4),
                      Bp + (size_t)(s * BK + row) * Ndim + chunk * 8);
            }
        }
    };

    load_stage(0, 0); CPA_COMMIT();
    load_stage(1, 1); CPA_COMMIT();
    load_stage(2, 2); CPA_COMMIT();

    int lr = lane & 15, lc = lane >> 4;
    for (int s = 0; s < NS; s++) {
        CPA_WAIT2();
        __syncthreads();
        if (s + 3 < NS) load_stage(s + 3, (s + 3) % NSTAGES);
        CPA_COMMIT();

        uint32_t aB = sb + (s % NSTAGES) * STAGE_B;
        uint32_t bB = aB + A_BYTES;
#pragma unroll
        for (int ks = 0; ks < 2; ks++) {
            uint32_t ah[4][4], bf[4][2];
#pragma unroll
            for (int bi = 0; bi < 2; bi++) {
                uint32_t t0, t1, t2, t3;
                int krow = ks * 16 + lr;
                int chunk = wn * 4 + bi * 2 + lc;
                uint32_t addr = bB + krow * 256 + ((chunk ^ (krow & 7)) << 4);
                LDSM4T(t0, t1, t2, t3, addr);
                // trans: m0=(k0-7,n0-7) m1=(k8-15,n0-7) m2=(k0-7,n8-15) m3=(k8-15,n8-15)
                bf[bi * 2 + 0][0] = t0; bf[bi * 2 + 0][1] = t1;
                bf[bi * 2 + 1][0] = t2; bf[bi * 2 + 1][1] = t3;
            }
#pragma unroll
            for (int mi = 0; mi < 4; mi++) {
                uint32_t addr = aB + (wm * 64 + mi * 16 + lr) * (SAROW * 2) + ks * 32 + lc * 16;
                LDSM4(ah[mi][0], ah[mi][1], ah[mi][2], ah[mi][3], addr);
            }
#pragma unroll
            for (int mi = 0; mi < 4; mi++)
#pragma unroll
                for (int ni = 0; ni < 4; ni++)
                    MMA16816(acc[mi][ni], ah[mi], bf[ni]);
        }
        __syncthreads();
    }

    int rbase = r0 + wm * 64 + (lane >> 2);
    int cbase = n0 + wn * 32 + (lane & 3) * 2;
#pragma unroll
    for (int mi = 0; mi < 4; mi++) {
#pragma unroll
        for (int ni = 0; ni < 4; ni++) {
#pragma unroll
            for (int half = 0; half < 2; half++) {
                int r = rbase + mi * 16 + half * 8;
                int c = cbase + ni * 8;
                float v0 = acc[mi][ni][half * 2 + 0];
                float v1 = acc[mi][ni][half * 2 + 1];
                if (GELU) {
                    __half2 hh = __halves2half2(__float2half_rn(gelu_f(v0)),
                                                __float2half_rn(gelu_f(v1)));
                    *reinterpret_cast<__half2*>(&OutH[(size_t)r * FF + c]) = hh;
                } else {
                    float2 o; o.x = v0; o.y = v1;
                    *reinterpret_cast<float2*>(&OutF[(size_t)r * HD + c]) = o;
                }
            }
        }
    }
}

// ---------------- 7. combine ----------------
__global__ __launch_bounds__(256) void combine_kernel(float* __restrict__ out) {
    int t = blockIdx.x;
    int r0 = g_t2r[t * 2], r1 = g_t2r[t * 2 + 1];
    float w0 = g_topw[t * 2], w1 = g_topw[t * 2 + 1];
    int c = threadIdx.x * 4;
    float4 a = *reinterpret_cast<const float4*>(g_o + (size_t)r0 * HD + c);
    float4 b = *reinterpret_cast<const float4*>(g_o + (size_t)r1 * HD + c);
    float4 o;
    o.x = w0 * a.x + w1 * b.x;
    o.y = w0 * a.y + w1 * b.y;
    o.z = w0 * a.z + w1 * b.z;
    o.w = w0 * a.w + w1 * b.w;
    *reinterpret_cast<float4*>(out + (size_t)t * HD + c) = o;
}

// ---------------- 8. aux loss ----------------
__global__ __launch_bounds__(256) void aux_kernel(const float* __restrict__ logits,
                                                  float* __restrict__ aux_out) {
    __shared__ float red[256][17];
    float acc[NE], freq[NE];
#pragma unroll
    for (int e = 0; e < NE; e++) { acc[e] = 0.f; freq[e] = 0.f; }
    float z = 0.f;
    for (int t = threadIdx.x; t < NTOK; t += 256) {
        float l[NE];
#pragma unroll
        for (int e = 0; e < NE; e++) l[e] = logits[(size_t)t * NE + e];
        float m = l[0];
#pragma unroll
        for (int e = 1; e < NE; e++) m = fmaxf(m, l[e]);
        float p[NE], s = 0.f;
#pragma unroll
        for (int e = 0; e < NE; e++) { p[e] = expf(l[e] - m); s += p[e]; }
        float inv = 1.f / s;
#pragma unroll
        for (int e = 0; e < NE; e++) acc[e] += p[e] * inv;
        float lse = m + logf(s);
        z += lse * lse;
        int e0 = 0;
#pragma unroll
        for (int e = 1; e < NE; e++) if (l[e] > l[e0]) e0 = e;
        int e1 = (e0 == 0) ? 1 : 0;
#pragma unroll
        for (int e = 0; e < NE; e++) if (e != e0 && l[e] > l[e1]) e1 = e;
        freq[e0] += 1.f; freq[e1] += 1.f;
    }
    int tid = threadIdx.x;
#pragma unroll
    for (int e = 0; e < NE; e++) { red[tid][e] = acc[e]; red[tid][8 + e] = freq[e]; }
    red[tid][16] = z;
    __syncthreads();
    for (int s2 = 128; s2; s2 >>= 1) {
        if (tid < s2)
#pragma unroll
            for (int c = 0; c < 17; c++) red[tid][c] += red[tid + s2][c];
        __syncthreads();
    }
    if (tid == 0) {
        float sp = 0.f, sf = 0.f;
#pragma unroll
        for (int e = 0; e < NE; e++) { sp += red[0][e]; sf += red[0][8 + e]; }
        float sw = 0.f;
#pragma unroll
        for (int e = 0; e < NE; e++) sw += (red[0][e] / sp) * (red[0][8 + e] / sf);
        sw *= (float)NE;
        float zl = red[0][16] / (float)NTOK;
        aux_out[0] = sw + 0.1f * zl;
    }
}

// ---------------- entry ----------------
extern "C" void kernel_launch(void* const* d_in, const int* in_sizes, int n_in,
                              void* d_out, int out_size) {
    const float* x  = (const float*)d_in[0];
    const float* Wg = (const float*)d_in[1];
    const float* W1 = (const float*)d_in[2];
    const float* W2 = (const float*)d_in[3];
    float* out    = (float*)d_out;
    float* logits = out + (size_t)NTOK * HD;
    float* aux    = logits + (size_t)NTOK * NE;

    cudaFuncSetAttribute(mma_gemm_kernel<HD, true>,
                         cudaFuncAttributeMaxDynamicSharedMemorySize, SM_TOT);
    cudaFuncSetAttribute(mma_gemm_kernel<FF, false>,
                         cudaFuncAttributeMaxDynamicSharedMemorySize, SM_TOT);

    __half *xh, *w1h, *w2h, *h1;
    float* o_ptr;
    cudaGetSymbolAddress((void**)&xh,  g_xh);
    cudaGetSymbolAddress((void**)&w1h, g_w1h);
    cudaGetSymbolAddress((void**)&w2h, g_w2h);
    cudaGetSymbolAddress((void**)&h1,  g_h1);
    cudaGetSymbolAddress((void**)&o_ptr, g_o);

    const size_t WN4 = (size_t)NE * HD * FF / 4;   // float4 count per weight tensor

    init_kernel<<<1, 32>>>();
    router_kernel<<<NTOK, 128>>>(x, Wg, logits);
    offsets_kernel<<<1, 1>>>();
    scatter_kernel<<<NTOK, 128>>>(x);
    wconv_kernel<<<1024, 256>>>(W1, w1h, WN4);
    // GEMM1 (+ fused W2 convert in the extra blockIdx.y slice)
    mma_gemm_kernel<HD, true><<<dim3(MTILES, FF / BN + 1), 256, SM_TOT>>>(
        xh, w1h, FF, h1, nullptr, W2, w2h, WN4);
    // GEMM2
    mma_gemm_kernel<FF, false><<<dim3(MTILES, HD / BN), 256, SM_TOT>>>(
        h1, w2h, HD, nullptr, o_ptr, nullptr, nullptr, 0);
    combine_kernel<<<NTOK, 256>>>(out);
    aux_kernel<<<1, 256>>>(logits, aux);
}